// round 1
// baseline (speedup 1.0000x reference)
#include <cuda_runtime.h>
#include <math.h>

// ---------------------------------------------------------------------------
// WindowAttentionV2: SwinV2 window attention
//   x[2048,64,512] -> qkv GEMM -> cosine attn (16 heads, d=32) + CPB bias
//   + mask -> softmax -> @v -> proj GEMM -> out[2048,64,512]
// ---------------------------------------------------------------------------

#define B_WIN   2048
#define N_TOK   64
#define CHN     512
#define NHEAD   16
#define HDIM    32
#define NW      256
#define M_TOTAL (B_WIN * N_TOK)            // 131072
#define LOG_SCALE_MAX 4.6051702f           // ln(100)

// Scratch (device globals: allocation-free per harness rules)
__device__ float g_qkv[(size_t)M_TOTAL * 3 * CHN];   // 805 MB
__device__ float g_att[(size_t)M_TOTAL * CHN];       // 256 MB
__device__ float g_qkvbias[3 * CHN];
__device__ float g_scales[NHEAD];
__device__ float g_tab[225 * NHEAD];
__device__ float g_bias[NHEAD * N_TOK * N_TOK];

// ---------------------------------------------------------------------------
// Small prep: qkv bias concat + per-head logit scale
// ---------------------------------------------------------------------------
__global__ void prep_kernel(const float* __restrict__ q_bias,
                            const float* __restrict__ v_bias,
                            const float* __restrict__ logit_scale,
                            float* __restrict__ qkvbias,
                            float* __restrict__ scales) {
    int t = blockIdx.x * blockDim.x + threadIdx.x;
    if (t < 512)       qkvbias[t] = q_bias[t];
    else if (t < 1024) qkvbias[t] = 0.0f;
    else if (t < 1536) qkvbias[t] = v_bias[t - 1024];
    else if (t < 1536 + NHEAD) {
        float ls = logit_scale[t - 1536];
        scales[t - 1536] = expf(fminf(ls, LOG_SCALE_MAX));
    }
}

// ---------------------------------------------------------------------------
// CPB MLP: tab[225,16] = relu(rel_table @ w1 + b1) @ w2
// ---------------------------------------------------------------------------
__global__ void cpb_kernel(const float* __restrict__ rel,
                           const float* __restrict__ w1,
                           const float* __restrict__ b1,
                           const float* __restrict__ w2,
                           float* __restrict__ tab) {
    int t = blockIdx.x * blockDim.x + threadIdx.x;
    if (t >= 225 * NHEAD) return;
    int r = t >> 4, h = t & 15;
    float t0 = rel[r * 2], t1 = rel[r * 2 + 1];
    float acc = 0.0f;
    for (int j = 0; j < 512; j++) {
        float hid = fmaf(t0, w1[j], fmaf(t1, w1[512 + j], b1[j]));
        hid = fmaxf(hid, 0.0f);
        acc = fmaf(hid, w2[j * NHEAD + h], acc);
    }
    tab[t] = acc;
}

// ---------------------------------------------------------------------------
// Expand CPB table to bias[h,64,64] = 16*sigmoid(tab[idx(i,j), h])
// ---------------------------------------------------------------------------
__global__ void bias_kernel(const float* __restrict__ tab,
                            float* __restrict__ bias) {
    int e = blockIdx.x * blockDim.x + threadIdx.x;   // 65536
    int h  = e >> 12;
    int ij = e & 4095;
    int i = ij >> 6, j = ij & 63;
    int dh = (i >> 3) - (j >> 3) + 7;
    int dw = (i & 7)  - (j & 7)  + 7;
    float v = tab[(dh * 15 + dw) * NHEAD + h];
    bias[e] = 16.0f / (1.0f + expf(-v));
}

// ---------------------------------------------------------------------------
// SGEMM: C[M,N] = A[M,K] @ B[K,N] + bias[N]   (128x128x8 tile, 8x8/thread)
// M,N multiples of 128, K multiple of 8.
// ---------------------------------------------------------------------------
__global__ __launch_bounds__(256, 2) void sgemm_bias(
    const float* __restrict__ A, const float* __restrict__ B,
    const float* __restrict__ bias, float* __restrict__ C,
    int M, int N, int K)
{
    __shared__ float As[8][128];
    __shared__ float Bs[8][132];

    const int tid  = threadIdx.x;
    const int row0 = blockIdx.y * 128;
    const int col0 = blockIdx.x * 128;

    const int arow = tid >> 1;
    const int ak   = (tid & 1) * 4;
    const int brow = tid >> 5;
    const int bcol = (tid & 31) * 4;

    const float* Ap = A + (size_t)(row0 + arow) * K + ak;
    const float* Bp = B + (size_t)brow * N + col0 + bcol;

    const int ty = tid >> 4;     // 0..15 -> row group
    const int tx = tid & 15;     // 0..15 -> col group

    float acc[8][8];
#pragma unroll
    for (int i = 0; i < 8; i++)
#pragma unroll
        for (int j = 0; j < 8; j++) acc[i][j] = 0.0f;

    for (int kt = 0; kt < K; kt += 8) {
        float4 av = *(const float4*)Ap;  Ap += 8;
        float4 bv = *(const float4*)Bp;  Bp += (size_t)8 * N;

        As[ak + 0][arow] = av.x;
        As[ak + 1][arow] = av.y;
        As[ak + 2][arow] = av.z;
        As[ak + 3][arow] = av.w;
        *(float4*)&Bs[brow][bcol] = bv;
        __syncthreads();

#pragma unroll
        for (int kk = 0; kk < 8; kk++) {
            float a[8], b[8];
            *(float4*)(a)     = *(const float4*)&As[kk][ty * 8];
            *(float4*)(a + 4) = *(const float4*)&As[kk][ty * 8 + 4];
            *(float4*)(b)     = *(const float4*)&Bs[kk][tx * 8];
            *(float4*)(b + 4) = *(const float4*)&Bs[kk][tx * 8 + 4];
#pragma unroll
            for (int i = 0; i < 8; i++)
#pragma unroll
                for (int j = 0; j < 8; j++)
                    acc[i][j] = fmaf(a[i], b[j], acc[i][j]);
        }
        __syncthreads();
    }

#pragma unroll
    for (int i = 0; i < 8; i++) {
        int row = row0 + ty * 8 + i;
        float* Cp = C + (size_t)row * N + col0 + tx * 8;
#pragma unroll
        for (int j = 0; j < 8; j++)
            Cp[j] = acc[i][j] + bias[col0 + tx * 8 + j];
    }
}

// ---------------------------------------------------------------------------
// Fused per-(window, head) attention:
//   normalize q,k (fold exp(logit_scale)); S = qn@kn^T + bias[h] + mask[w];
//   softmax rows; O = S@v -> att[(b*64+i)*512 + h*32 + d]
// ---------------------------------------------------------------------------
__global__ __launch_bounds__(256) void attn_kernel(
    const float* __restrict__ qkv,   // [131072, 1536]
    const float* __restrict__ mask,  // [256, 64, 64]
    const float* __restrict__ bias,  // [16, 64, 64]
    const float* __restrict__ scales,
    float* __restrict__ out)         // [131072, 512] in [b][n][h][d]
{
    const int h = blockIdx.x;
    const int b = blockIdx.y;
    const int tid = threadIdx.x;

    __shared__ float qs[64][33];
    __shared__ float ks[64][33];
    __shared__ float vs[64][33];
    __shared__ float S[64][65];

    const float* base = qkv + (size_t)b * N_TOK * (3 * CHN) + h * HDIM;
    for (int e = tid; e < 64 * 32; e += 256) {
        int i = e >> 5, dd = e & 31;
        const float* row = base + (size_t)i * (3 * CHN) + dd;
        qs[i][dd] = row[0];
        ks[i][dd] = row[CHN];
        vs[i][dd] = row[2 * CHN];
    }
    __syncthreads();

    // normalize q (with scale folded) and k
    if (tid < 128) {
        float* rowp = (tid < 64) ? qs[tid] : ks[tid - 64];
        float ss = 0.0f;
#pragma unroll
        for (int kk = 0; kk < 32; kk++) { float v = rowp[kk]; ss = fmaf(v, v, ss); }
        float inv = rsqrtf(fmaxf(ss, 1e-24f));
        if (tid < 64) inv *= scales[h];
#pragma unroll
        for (int kk = 0; kk < 32; kk++) rowp[kk] *= inv;
    }
    __syncthreads();

    // scores
    const float* mrow = mask + (size_t)(b & (NW - 1)) * 4096;
    const float* brow = bias + (size_t)h * 4096;
    for (int e = tid; e < 4096; e += 256) {
        int i = e >> 6, j = e & 63;
        float acc = 0.0f;
#pragma unroll
        for (int kk = 0; kk < 32; kk++) acc = fmaf(qs[i][kk], ks[j][kk], acc);
        S[i][j] = acc + brow[e] + mrow[e];
    }
    __syncthreads();

    // softmax: 8 warps x 8 rows each, 2 cols/lane
    const int warp = tid >> 5, lane = tid & 31;
    for (int r = warp; r < 64; r += 8) {
        float v0 = S[r][lane], v1 = S[r][lane + 32];
        float m = fmaxf(v0, v1);
#pragma unroll
        for (int o = 16; o; o >>= 1) m = fmaxf(m, __shfl_xor_sync(0xffffffffu, m, o));
        float e0 = __expf(v0 - m), e1 = __expf(v1 - m);
        float s = e0 + e1;
#pragma unroll
        for (int o = 16; o; o >>= 1) s += __shfl_xor_sync(0xffffffffu, s, o);
        float invs = 1.0f / s;
        S[r][lane]      = e0 * invs;
        S[r][lane + 32] = e1 * invs;
    }
    __syncthreads();

    // O = S @ v ; write to [b][i][h][d] layout
    float* orow = out + (size_t)b * N_TOK * CHN + h * HDIM;
    for (int e = tid; e < 64 * 32; e += 256) {
        int i = e >> 5, dd = e & 31;
        float acc = 0.0f;
#pragma unroll
        for (int m2 = 0; m2 < 64; m2++) acc = fmaf(S[i][m2], vs[m2][dd], acc);
        orow[(size_t)i * CHN + dd] = acc;
    }
}

// ---------------------------------------------------------------------------
// Launch
// ---------------------------------------------------------------------------
extern "C" void kernel_launch(void* const* d_in, const int* in_sizes, int n_in,
                              void* d_out, int out_size)
{
    const float* x      = (const float*)d_in[0];
    const float* mask   = (const float*)d_in[1];
    const float* rel    = (const float*)d_in[2];
    const float* w_qkv  = (const float*)d_in[3];
    const float* q_bias = (const float*)d_in[4];
    const float* v_bias = (const float*)d_in[5];
    const float* lscale = (const float*)d_in[6];
    const float* cpb_w1 = (const float*)d_in[7];
    const float* cpb_b1 = (const float*)d_in[8];
    const float* cpb_w2 = (const float*)d_in[9];
    const float* proj_w = (const float*)d_in[10];
    const float* proj_b = (const float*)d_in[11];
    float* out = (float*)d_out;

    float *qkv, *att, *qkvbias, *scales, *tab, *bias;
    cudaGetSymbolAddress((void**)&qkv,     g_qkv);
    cudaGetSymbolAddress((void**)&att,     g_att);
    cudaGetSymbolAddress((void**)&qkvbias, g_qkvbias);
    cudaGetSymbolAddress((void**)&scales,  g_scales);
    cudaGetSymbolAddress((void**)&tab,     g_tab);
    cudaGetSymbolAddress((void**)&bias,    g_bias);

    prep_kernel<<<7, 256>>>(q_bias, v_bias, lscale, qkvbias, scales);
    cpb_kernel<<<15, 256>>>(rel, cpb_w1, cpb_b1, cpb_w2, tab);
    bias_kernel<<<256, 256>>>(tab, bias);

    // qkv = x @ w_qkv + qkv_bias : [131072,512] x [512,1536]
    sgemm_bias<<<dim3(1536 / 128, M_TOTAL / 128), 256>>>(
        x, w_qkv, qkvbias, qkv, M_TOTAL, 3 * CHN, CHN);

    // fused window attention
    attn_kernel<<<dim3(NHEAD, B_WIN), 256>>>(qkv, mask, bias, scales, att);

    // out = att @ proj_w + proj_b : [131072,512] x [512,512]
    sgemm_bias<<<dim3(CHN / 128, M_TOTAL / 128), 256>>>(
        att, proj_w, proj_b, out, M_TOTAL, CHN, CHN);
}

// round 2
// speedup vs baseline: 2.2555x; 2.2555x over previous
#include <cuda_runtime.h>
#include <math.h>
#include <stdint.h>

// ---------------------------------------------------------------------------
// WindowAttentionV2: SwinV2 window attention
//   x[2048,64,512] -> qkv GEMM (tf32 TC) -> cosine attn (16 heads, d=32)
//   + CPB bias + mask -> softmax -> @v -> proj GEMM (tf32 TC)
// ---------------------------------------------------------------------------

#define B_WIN   2048
#define N_TOK   64
#define CHN     512
#define NHEAD   16
#define HDIM    32
#define NW      256
#define M_TOTAL (B_WIN * N_TOK)            // 131072
#define LOG_SCALE_MAX 4.6051702f           // ln(100)

// Scratch (device globals: allocation-free per harness rules)
__device__ float g_qkv[(size_t)M_TOTAL * 3 * CHN];
__device__ float g_att[(size_t)M_TOTAL * CHN];
__device__ float g_qkvbias[3 * CHN];
__device__ float g_scales[NHEAD];
__device__ float g_tab[225 * NHEAD];
__device__ float g_bias[NHEAD * N_TOK * N_TOK];

// ---------------------------------------------------------------------------
__global__ void prep_kernel(const float* __restrict__ q_bias,
                            const float* __restrict__ v_bias,
                            const float* __restrict__ logit_scale,
                            float* __restrict__ qkvbias,
                            float* __restrict__ scales) {
    int t = blockIdx.x * blockDim.x + threadIdx.x;
    if (t < 512)       qkvbias[t] = q_bias[t];
    else if (t < 1024) qkvbias[t] = 0.0f;
    else if (t < 1536) qkvbias[t] = v_bias[t - 1024];
    else if (t < 1536 + NHEAD) {
        float ls = logit_scale[t - 1536];
        scales[t - 1536] = expf(fminf(ls, LOG_SCALE_MAX));
    }
}

__global__ void cpb_kernel(const float* __restrict__ rel,
                           const float* __restrict__ w1,
                           const float* __restrict__ b1,
                           const float* __restrict__ w2,
                           float* __restrict__ tab) {
    int t = blockIdx.x * blockDim.x + threadIdx.x;
    if (t >= 225 * NHEAD) return;
    int r = t >> 4, h = t & 15;
    float t0 = rel[r * 2], t1 = rel[r * 2 + 1];
    float acc = 0.0f;
    for (int j = 0; j < 512; j++) {
        float hid = fmaf(t0, w1[j], fmaf(t1, w1[512 + j], b1[j]));
        hid = fmaxf(hid, 0.0f);
        acc = fmaf(hid, w2[j * NHEAD + h], acc);
    }
    tab[t] = acc;
}

__global__ void bias_kernel(const float* __restrict__ tab,
                            float* __restrict__ bias) {
    int e = blockIdx.x * blockDim.x + threadIdx.x;   // 65536
    int h  = e >> 12;
    int ij = e & 4095;
    int i = ij >> 6, j = ij & 63;
    int dh = (i >> 3) - (j >> 3) + 7;
    int dw = (i & 7)  - (j & 7)  + 7;
    float v = tab[(dh * 15 + dw) * NHEAD + h];
    bias[e] = 16.0f / (1.0f + expf(-v));
}

// ---------------------------------------------------------------------------
// TF32 tensor-core GEMM: C[M,N] = A[M,K]@B[K,N] + bias[N]
// CTA tile 128x128x16, 8 warps (2x4), each warp 64x32 via m16n8k8.
// ---------------------------------------------------------------------------
__device__ __forceinline__ float tf32r(float x) {
    uint32_t u;
    asm("cvt.rna.tf32.f32 %0, %1;" : "=r"(u) : "f"(x));
    return __uint_as_float(u);
}

__device__ __forceinline__ void ldsm4(uint32_t& r0, uint32_t& r1,
                                      uint32_t& r2, uint32_t& r3, uint32_t addr) {
    asm volatile("ldmatrix.sync.aligned.m8n8.x4.shared.b16 {%0,%1,%2,%3}, [%4];"
                 : "=r"(r0), "=r"(r1), "=r"(r2), "=r"(r3) : "r"(addr));
}

__device__ __forceinline__ void mma_tf32(float* c, const uint32_t* a,
                                         uint32_t b0, uint32_t b1) {
    asm volatile(
        "mma.sync.aligned.m16n8k8.row.col.f32.tf32.tf32.f32 "
        "{%0,%1,%2,%3}, {%4,%5,%6,%7}, {%8,%9}, {%0,%1,%2,%3};"
        : "+f"(c[0]), "+f"(c[1]), "+f"(c[2]), "+f"(c[3])
        : "r"(a[0]), "r"(a[1]), "r"(a[2]), "r"(a[3]), "r"(b0), "r"(b1));
}

#define APAD 20    // A smem row pitch (floats): 16B aligned + distinct ldsm banks
#define BPAD 136   // B smem row pitch (floats): conflict-free frag LDS & STS

__global__ __launch_bounds__(256, 2) void gemm_tf32(
    const float* __restrict__ A, const float* __restrict__ B,
    const float* __restrict__ bias, float* __restrict__ C,
    int M, int N, int K)
{
    __shared__ float As[128][APAD];   // [m][k]
    __shared__ float Bs[16][BPAD];    // [k][n]

    const int tid  = threadIdx.x;
    const int lane = tid & 31;
    const int warp = tid >> 5;
    const int wm   = warp & 1;        // 0..1  -> 64-row slab
    const int wn   = warp >> 1;       // 0..3  -> 32-col slab
    const int row0 = blockIdx.y * 128;
    const int col0 = blockIdx.x * 128;

    // global load mapping
    const int ar = tid >> 2;          // 0..63
    const int ac = (tid & 3) * 4;     // 0,4,8,12
    const int br = tid >> 5;          // 0..7
    const int bc = (tid & 31) * 4;    // 0..124

    const float* Ap = A + (size_t)(row0 + ar) * K + ac;
    const float* Bp = B + (size_t)br * N + col0 + bc;

    const int g  = lane >> 2;         // 0..7
    const int tg = lane & 3;          // 0..3

    // ldmatrix per-lane A addresses (byte) for each of 4 m-tiles
    const int lr  = lane & 7;
    const int sel = lane >> 3;
    uint32_t as_base = (uint32_t)__cvta_generic_to_shared(&As[0][0]);
    uint32_t a_off[4];
#pragma unroll
    for (int mt = 0; mt < 4; mt++) {
        int rowm = wm * 64 + mt * 16 + lr + ((sel & 1) << 3);
        int colm = (sel & 2) << 1;
        a_off[mt] = as_base + (uint32_t)(rowm * APAD + colm) * 4u;
    }
    const int bcol = wn * 32;

    float acc[4][4][4];
#pragma unroll
    for (int mt = 0; mt < 4; mt++)
#pragma unroll
        for (int nt = 0; nt < 4; nt++)
#pragma unroll
            for (int i = 0; i < 4; i++) acc[mt][nt][i] = 0.0f;

    const int niter = K >> 4;
    float4 aR0 = *(const float4*)Ap;
    float4 aR1 = *(const float4*)(Ap + (size_t)64 * K);
    float4 bR0 = *(const float4*)Bp;
    float4 bR1 = *(const float4*)(Bp + (size_t)8 * N);

    for (int kt = 0; kt < niter; kt++) {
        // stage (with tf32 rounding)
        As[ar][ac + 0]      = tf32r(aR0.x);
        As[ar][ac + 1]      = tf32r(aR0.y);
        As[ar][ac + 2]      = tf32r(aR0.z);
        As[ar][ac + 3]      = tf32r(aR0.w);
        As[ar + 64][ac + 0] = tf32r(aR1.x);
        As[ar + 64][ac + 1] = tf32r(aR1.y);
        As[ar + 64][ac + 2] = tf32r(aR1.z);
        As[ar + 64][ac + 3] = tf32r(aR1.w);
        Bs[br][bc + 0]      = tf32r(bR0.x);
        Bs[br][bc + 1]      = tf32r(bR0.y);
        Bs[br][bc + 2]      = tf32r(bR0.z);
        Bs[br][bc + 3]      = tf32r(bR0.w);
        Bs[br + 8][bc + 0]  = tf32r(bR1.x);
        Bs[br + 8][bc + 1]  = tf32r(bR1.y);
        Bs[br + 8][bc + 2]  = tf32r(bR1.z);
        Bs[br + 8][bc + 3]  = tf32r(bR1.w);
        __syncthreads();

        // prefetch next tile
        if (kt + 1 < niter) {
            Ap += 16;
            Bp += (size_t)16 * N;
            aR0 = *(const float4*)Ap;
            aR1 = *(const float4*)(Ap + (size_t)64 * K);
            bR0 = *(const float4*)Bp;
            bR1 = *(const float4*)(Bp + (size_t)8 * N);
        }

        // compute: 2 k-steps of 8
#pragma unroll
        for (int ks = 0; ks < 2; ks++) {
            const int k0 = ks * 8;
            uint32_t af[4][4];
#pragma unroll
            for (int mt = 0; mt < 4; mt++)
                ldsm4(af[mt][0], af[mt][1], af[mt][2], af[mt][3],
                      a_off[mt] + (uint32_t)k0 * 4u);

            uint32_t bf[4][2];
#pragma unroll
            for (int nt = 0; nt < 4; nt++) {
                bf[nt][0] = __float_as_uint(Bs[k0 + tg][bcol + nt * 8 + g]);
                bf[nt][1] = __float_as_uint(Bs[k0 + tg + 4][bcol + nt * 8 + g]);
            }
#pragma unroll
            for (int mt = 0; mt < 4; mt++)
#pragma unroll
                for (int nt = 0; nt < 4; nt++)
                    mma_tf32(acc[mt][nt], af[mt], bf[nt][0], bf[nt][1]);
        }
        __syncthreads();
    }

    // epilogue
#pragma unroll
    for (int mt = 0; mt < 4; mt++) {
        int row = row0 + wm * 64 + mt * 16 + g;
#pragma unroll
        for (int nt = 0; nt < 4; nt++) {
            int col = col0 + wn * 32 + nt * 8 + tg * 2;
            float b0 = bias[col], b1 = bias[col + 1];
            float2 v0 = make_float2(acc[mt][nt][0] + b0, acc[mt][nt][1] + b1);
            float2 v1 = make_float2(acc[mt][nt][2] + b0, acc[mt][nt][3] + b1);
            *(float2*)(C + (size_t)row * N + col)       = v0;
            *(float2*)(C + (size_t)(row + 8) * N + col) = v1;
        }
    }
}

// ---------------------------------------------------------------------------
// Fused per-(window, head) attention (unchanged from R1)
// ---------------------------------------------------------------------------
__global__ __launch_bounds__(256) void attn_kernel(
    const float* __restrict__ qkv,   // [131072, 1536]
    const float* __restrict__ mask,  // [256, 64, 64]
    const float* __restrict__ bias,  // [16, 64, 64]
    const float* __restrict__ scales,
    float* __restrict__ out)         // [131072, 512]
{
    const int h = blockIdx.x;
    const int b = blockIdx.y;
    const int tid = threadIdx.x;

    __shared__ float qs[64][33];
    __shared__ float ks[64][33];
    __shared__ float vs[64][33];
    __shared__ float S[64][65];

    const float* base = qkv + (size_t)b * N_TOK * (3 * CHN) + h * HDIM;
    for (int e = tid; e < 64 * 32; e += 256) {
        int i = e >> 5, dd = e & 31;
        const float* row = base + (size_t)i * (3 * CHN) + dd;
        qs[i][dd] = row[0];
        ks[i][dd] = row[CHN];
        vs[i][dd] = row[2 * CHN];
    }
    __syncthreads();

    if (tid < 128) {
        float* rowp = (tid < 64) ? qs[tid] : ks[tid - 64];
        float ss = 0.0f;
#pragma unroll
        for (int kk = 0; kk < 32; kk++) { float v = rowp[kk]; ss = fmaf(v, v, ss); }
        float inv = rsqrtf(fmaxf(ss, 1e-24f));
        if (tid < 64) inv *= scales[h];
#pragma unroll
        for (int kk = 0; kk < 32; kk++) rowp[kk] *= inv;
    }
    __syncthreads();

    const float* mrow = mask + (size_t)(b & (NW - 1)) * 4096;
    const float* brow = bias + (size_t)h * 4096;
    for (int e = tid; e < 4096; e += 256) {
        int i = e >> 6, j = e & 63;
        float acc = 0.0f;
#pragma unroll
        for (int kk = 0; kk < 32; kk++) acc = fmaf(qs[i][kk], ks[j][kk], acc);
        S[i][j] = acc + brow[e] + mrow[e];
    }
    __syncthreads();

    const int warp = tid >> 5, lane = tid & 31;
    for (int r = warp; r < 64; r += 8) {
        float v0 = S[r][lane], v1 = S[r][lane + 32];
        float m = fmaxf(v0, v1);
#pragma unroll
        for (int o = 16; o; o >>= 1) m = fmaxf(m, __shfl_xor_sync(0xffffffffu, m, o));
        float e0 = __expf(v0 - m), e1 = __expf(v1 - m);
        float s = e0 + e1;
#pragma unroll
        for (int o = 16; o; o >>= 1) s += __shfl_xor_sync(0xffffffffu, s, o);
        float invs = 1.0f / s;
        S[r][lane]      = e0 * invs;
        S[r][lane + 32] = e1 * invs;
    }
    __syncthreads();

    float* orow = out + (size_t)b * N_TOK * CHN + h * HDIM;
    for (int e = tid; e < 64 * 32; e += 256) {
        int i = e >> 5, dd = e & 31;
        float acc = 0.0f;
#pragma unroll
        for (int m2 = 0; m2 < 64; m2++) acc = fmaf(S[i][m2], vs[m2][dd], acc);
        orow[(size_t)i * CHN + dd] = acc;
    }
}

// ---------------------------------------------------------------------------
extern "C" void kernel_launch(void* const* d_in, const int* in_sizes, int n_in,
                              void* d_out, int out_size)
{
    const float* x      = (const float*)d_in[0];
    const float* mask   = (const float*)d_in[1];
    const float* rel    = (const float*)d_in[2];
    const float* w_qkv  = (const float*)d_in[3];
    const float* q_bias = (const float*)d_in[4];
    const float* v_bias = (const float*)d_in[5];
    const float* lscale = (const float*)d_in[6];
    const float* cpb_w1 = (const float*)d_in[7];
    const float* cpb_b1 = (const float*)d_in[8];
    const float* cpb_w2 = (const float*)d_in[9];
    const float* proj_w = (const float*)d_in[10];
    const float* proj_b = (const float*)d_in[11];
    float* out = (float*)d_out;

    float *qkv, *att, *qkvbias, *scales, *tab, *bias;
    cudaGetSymbolAddress((void**)&qkv,     g_qkv);
    cudaGetSymbolAddress((void**)&att,     g_att);
    cudaGetSymbolAddress((void**)&qkvbias, g_qkvbias);
    cudaGetSymbolAddress((void**)&scales,  g_scales);
    cudaGetSymbolAddress((void**)&tab,     g_tab);
    cudaGetSymbolAddress((void**)&bias,    g_bias);

    prep_kernel<<<7, 256>>>(q_bias, v_bias, lscale, qkvbias, scales);
    cpb_kernel<<<15, 256>>>(rel, cpb_w1, cpb_b1, cpb_w2, tab);
    bias_kernel<<<256, 256>>>(tab, bias);

    // qkv = x @ w_qkv + qkv_bias : [131072,512] x [512,1536]
    gemm_tf32<<<dim3(1536 / 128, M_TOTAL / 128), 256>>>(
        x, w_qkv, qkvbias, qkv, M_TOTAL, 3 * CHN, CHN);

    attn_kernel<<<dim3(NHEAD, B_WIN), 256>>>(qkv, mask, bias, scales, att);

    // out = att @ proj_w + proj_b : [131072,512] x [512,512]
    gemm_tf32<<<dim3(CHN / 128, M_TOTAL / 128), 256>>>(
        att, proj_w, proj_b, out, M_TOTAL, CHN, CHN);
}